// round 2
// baseline (speedup 1.0000x reference)
#include <cuda_runtime.h>
#include <cuda_bf16.h>
#include <cstdint>

#define NN 4096
#define DD 128
#define NITER 100
#define EPSV 1e-8f
#define INV_N (1.0f/4096.0f)

// ---------- device scratch (static __device__ globals; no allocation) ----------
static __device__ __align__(16) __nv_bfloat16 g_K [(size_t)NN*NN];
static __device__ __align__(16) __nv_bfloat16 g_KT[(size_t)NN*NN];
static __device__ __align__(16) __nv_bfloat16 g_C [(size_t)NN*NN];
static __device__ float g_u[NN];
static __device__ float g_v[NN];
static __device__ float g_xsq[3][NN];
static __device__ float g_partials[3*512];

// ---------- helpers ----------
__device__ __forceinline__ float bl(unsigned w){ return __uint_as_float(w << 16); }
__device__ __forceinline__ float bh(unsigned w){ return __uint_as_float(w & 0xffff0000u); }
__device__ __forceinline__ unsigned pk(float a, float b){
    __nv_bfloat162 h = __float22bfloat162_rn(make_float2(a, b));
    return *reinterpret_cast<unsigned*>(&h);
}
// exp(-20*c) for c in [0, ~0.3], FMA-pipe only (no MUFU). rel err ~3e-6.
__device__ __forceinline__ float exp_n20(float c){
    float t = c * -28.853900817779268f;       // -20/ln(2) * c  => 2^t
    int   i = __float2int_rn(t);
    float g = (t - (float)i) * 0.6931471805599453f;   // |g| <= 0.347
    float p = 1.0f + g*(1.0f + g*(0.5f + g*(0.16666666666f
              + g*(0.04166666666f + g*0.00833333333f))));
    return __uint_as_float(__float_as_uint(p) + (i << 23));
}
__device__ __forceinline__ float warp_sum(float v){
    #pragma unroll
    for (int o = 16; o; o >>= 1) v += __shfl_xor_sync(0xffffffffu, v, o);
    return v;
}

// ---------- row squared norms of all three inputs ----------
__global__ __launch_bounds__(256) void sq_kernel(const float* __restrict__ z0,
                                                 const float* __restrict__ z1,
                                                 const float* __restrict__ z2){
    int warp = threadIdx.x >> 5, lane = threadIdx.x & 31;
    int gr = blockIdx.x * 8 + warp;           // 0..12287
    int m = gr >> 12, r = gr & (NN - 1);
    const float* z = (m == 0) ? z0 : ((m == 1) ? z1 : z2);
    float4 f = ((const float4*)(z + (size_t)r * DD))[lane];
    float s = f.x*f.x + f.y*f.y + f.z*f.z + f.w*f.w;
    s = warp_sum(s);
    if (lane == 0) g_xsq[m][r] = s;
}

__global__ void init_u(){ g_u[blockIdx.x * 256 + threadIdx.x] = 1.0f; }

// ---------- build K (bf16), K^T (bf16), C (bf16) for one pair ----------
__global__ __launch_bounds__(256) void build_kernel(const float* __restrict__ X,
                                                    const float* __restrict__ Y,
                                                    int sa, int sb){
    __shared__ __align__(16) float sm[2][32][128];  // 32 KB; reused as bf16 K tile later
    int tid = threadIdx.x;
    int tx = tid & 15, ty = tid >> 4;
    int cb = blockIdx.x * 128, rb = blockIdx.y * 128;

    float acc[8][8];
    #pragma unroll
    for (int i = 0; i < 8; i++)
        #pragma unroll
        for (int j = 0; j < 8; j++) acc[i][j] = 0.0f;

    for (int kc = 0; kc < DD; kc += 32){
        #pragma unroll
        for (int p = 0; p < 4; p++){
            int idx = tid + p * 256;          // float4 index 0..1023
            int r = idx >> 3, kq = idx & 7;
            float4 vx = *(const float4*)(X + (size_t)(rb + r) * DD + kc + kq * 4);
            sm[0][kq*4+0][r] = vx.x; sm[0][kq*4+1][r] = vx.y;
            sm[0][kq*4+2][r] = vx.z; sm[0][kq*4+3][r] = vx.w;
            float4 vy = *(const float4*)(Y + (size_t)(cb + r) * DD + kc + kq * 4);
            sm[1][kq*4+0][r] = vy.x; sm[1][kq*4+1][r] = vy.y;
            sm[1][kq*4+2][r] = vy.z; sm[1][kq*4+3][r] = vy.w;
        }
        __syncthreads();
        #pragma unroll
        for (int kk = 0; kk < 32; kk++){
            float a[8], b[8];
            *(float4*)(a)     = *(const float4*)&sm[0][kk][ty*8];
            *(float4*)(a + 4) = *(const float4*)&sm[0][kk][ty*8 + 4];
            *(float4*)(b)     = *(const float4*)&sm[1][kk][tx*8];
            *(float4*)(b + 4) = *(const float4*)&sm[1][kk][tx*8 + 4];
            #pragma unroll
            for (int i = 0; i < 8; i++)
                #pragma unroll
                for (int j = 0; j < 8; j++)
                    acc[i][j] = fmaf(a[i], b[j], acc[i][j]);
        }
        __syncthreads();
    }

    int r0 = rb + ty * 8, c0 = cb + tx * 8;
    float xsr[8], ysc[8];
    #pragma unroll
    for (int i = 0; i < 8; i++) xsr[i] = g_xsq[sa][r0 + i];
    #pragma unroll
    for (int j = 0; j < 8; j++) ysc[j] = g_xsq[sb][c0 + j];

    unsigned short* Ks = (unsigned short*)sm;   // 128x128 bf16 staging = 32 KB

    #pragma unroll
    for (int i = 0; i < 8; i++){
        float kv[8], cv[8];
        #pragma unroll
        for (int j = 0; j < 8; j++){
            float c = fmaxf(fmaf(-2.0f, acc[i][j], xsr[i] + ysc[j]), 0.0f);
            cv[j] = c;
            kv[j] = exp_n20(c);
        }
        uint4 kp = make_uint4(pk(kv[0],kv[1]), pk(kv[2],kv[3]), pk(kv[4],kv[5]), pk(kv[6],kv[7]));
        uint4 cp = make_uint4(pk(cv[0],cv[1]), pk(cv[2],cv[3]), pk(cv[4],cv[5]), pk(cv[6],cv[7]));
        *(uint4*)(g_K + (size_t)(r0 + i) * NN + c0) = kp;
        *(uint4*)(g_C + (size_t)(r0 + i) * NN + c0) = cp;
        *(uint4*)(Ks + ((ty*8 + i) * 128 + tx*8)) = kp;   // tile-local staging
    }
    __syncthreads();

    // coalesced transposed store of K tile -> g_KT
    int tc = tid >> 1, h = tid & 1;
    #pragma unroll
    for (int gr = 0; gr < 8; gr++){
        int rbase = h * 64 + gr * 8;
        unsigned s0 = Ks[(rbase+0)*128 + tc];
        unsigned s1 = Ks[(rbase+1)*128 + tc];
        unsigned s2 = Ks[(rbase+2)*128 + tc];
        unsigned s3 = Ks[(rbase+3)*128 + tc];
        unsigned s4 = Ks[(rbase+4)*128 + tc];
        unsigned s5 = Ks[(rbase+5)*128 + tc];
        unsigned s6 = Ks[(rbase+6)*128 + tc];
        unsigned s7 = Ks[(rbase+7)*128 + tc];
        uint4 v = make_uint4(s0 | (s1<<16), s2 | (s3<<16), s4 | (s5<<16), s6 | (s7<<16));
        *(uint4*)(g_KT + (size_t)(cb + tc) * NN + rb + rbase) = v;
    }
}

// ---------- one Sinkhorn half-step: y[r] = (1/n) / (dot(A[r,:], x) + eps) ----------
// which==0: A=K^T, x=u, y=v    which==1: A=K, x=v, y=u
__global__ __launch_bounds__(256) void matvec_kernel(int which){
    __shared__ __align__(16) float xs[NN];
    const __nv_bfloat16* __restrict__ A = which ? g_K : g_KT;
    const float* __restrict__ x = which ? g_v : g_u;
    float* __restrict__ y = which ? g_u : g_v;

    for (int i = threadIdx.x; i < NN/4; i += 256)
        ((float4*)xs)[i] = ((const float4*)x)[i];
    __syncthreads();

    int warp = threadIdx.x >> 5, lane = threadIdx.x & 31;
    int row = blockIdx.x * 8 + warp;
    const uint4* __restrict__ Ar = (const uint4*)(A + ((size_t)row << 12));

    float acc = 0.0f;
    #pragma unroll 8
    for (int it = 0; it < 16; it++){
        int s = lane + it * 32;
        uint4 w = Ar[s];
        const float4* xp = (const float4*)(xs + s * 8);
        float4 x0 = xp[0], x1 = xp[1];
        acc = fmaf(bl(w.x), x0.x, acc);
        acc = fmaf(bh(w.x), x0.y, acc);
        acc = fmaf(bl(w.y), x0.z, acc);
        acc = fmaf(bh(w.y), x0.w, acc);
        acc = fmaf(bl(w.z), x1.x, acc);
        acc = fmaf(bh(w.z), x1.y, acc);
        acc = fmaf(bl(w.w), x1.z, acc);
        acc = fmaf(bh(w.w), x1.w, acc);
    }
    acc = warp_sum(acc);
    if (lane == 0) y[row] = INV_N / (acc + EPSV);
}

// ---------- loss = sum_ij u_i K_ij v_j C_ij  (deterministic block partials) ----------
__global__ __launch_bounds__(256) void loss_kernel(int pair){
    __shared__ __align__(16) float vs[NN];
    __shared__ float red[8];
    for (int i = threadIdx.x; i < NN/4; i += 256)
        ((float4*)vs)[i] = ((const float4*)g_v)[i];
    __syncthreads();

    int warp = threadIdx.x >> 5, lane = threadIdx.x & 31;
    int row = blockIdx.x * 8 + warp;
    const uint4* __restrict__ Kr = (const uint4*)(g_K + ((size_t)row << 12));
    const uint4* __restrict__ Cr = (const uint4*)(g_C + ((size_t)row << 12));

    float acc = 0.0f;
    #pragma unroll 4
    for (int it = 0; it < 16; it++){
        int s = lane + it * 32;
        uint4 wk = Kr[s], wc = Cr[s];
        const float4* vp = (const float4*)(vs + s * 8);
        float4 v0 = vp[0], v1 = vp[1];
        acc = fmaf(bl(wk.x) * bl(wc.x), v0.x, acc);
        acc = fmaf(bh(wk.x) * bh(wc.x), v0.y, acc);
        acc = fmaf(bl(wk.y) * bl(wc.y), v0.z, acc);
        acc = fmaf(bh(wk.y) * bh(wc.y), v0.w, acc);
        acc = fmaf(bl(wk.z) * bl(wc.z), v1.x, acc);
        acc = fmaf(bh(wk.z) * bh(wc.z), v1.y, acc);
        acc = fmaf(bl(wk.w) * bl(wc.w), v1.z, acc);
        acc = fmaf(bh(wk.w) * bh(wc.w), v1.w, acc);
    }
    acc = warp_sum(acc);
    if (lane == 0) red[warp] = acc * g_u[row];
    __syncthreads();
    if (threadIdx.x == 0){
        float s = 0.0f;
        #pragma unroll
        for (int w = 0; w < 8; w++) s += red[w];
        g_partials[pair * 512 + blockIdx.x] = s;
    }
}

__global__ void finalize_kernel(float* __restrict__ out){
    __shared__ float red[512];
    int tid = threadIdx.x;
    float s = g_partials[tid] + g_partials[tid + 512] + g_partials[tid + 1024];
    red[tid] = s;
    __syncthreads();
    #pragma unroll
    for (int o = 256; o; o >>= 1){
        if (tid < o) red[tid] += red[tid + o];
        __syncthreads();
    }
    if (tid == 0) out[0] = red[0] * (1.0f / 3.0f);
}

// ---------- launch ----------
extern "C" void kernel_launch(void* const* d_in, const int* in_sizes, int n_in,
                              void* d_out, int out_size){
    const float* z[3] = { (const float*)d_in[0], (const float*)d_in[1], (const float*)d_in[2] };

    sq_kernel<<<1536, 256>>>(z[0], z[1], z[2]);

    const int pa[3] = {0, 0, 1};
    const int pb[3] = {1, 2, 2};
    for (int p = 0; p < 3; p++){
        build_kernel<<<dim3(32, 32), 256>>>(z[pa[p]], z[pb[p]], pa[p], pb[p]);
        init_u<<<16, 256>>>();
        for (int t = 0; t < NITER; t++){
            matvec_kernel<<<512, 256>>>(0);   // v = nu / (K^T u + eps)
            matvec_kernel<<<512, 256>>>(1);   // u = mu / (K v + eps)
        }
        loss_kernel<<<512, 256>>>(p);
    }
    finalize_kernel<<<1, 512>>>((float*)d_out);
}